// round 13
// baseline (speedup 1.0000x reference)
#include <cuda_runtime.h>
#include <cuda_bf16.h>
#include <math.h>
#include <stdint.h>

#define NN   8192
#define DIN  512
#define DD   64

// ===========================================================================
// Device globals (no allocation allowed).
// ===========================================================================
__device__ __nv_bfloat16  g_khhi[NN * DD];
__device__ __nv_bfloat16  g_khlo[NN * DD];
__device__ __nv_bfloat16  g_vhhi[NN * DD];
__device__ __nv_bfloat16  g_vhlo[NN * DD];
__device__ float          g_norm[NN];
__device__ unsigned       g_maxnorm_bits;   // reset in prep CTA0; atomicMax after
__device__ unsigned       g_mask[NN * (NN / 32)];   // 8MB bitmask

// ===========================================================================
// Helpers
// ===========================================================================
__device__ __forceinline__ uint32_t smem_u32(const void* p) {
    uint32_t a;
    asm("{ .reg .u64 t; cvta.to.shared.u64 t, %1; cvt.u32.u64 %0, t; }"
        : "=r"(a) : "l"(p));
    return a;
}
#define SW128(x) ((uint32_t)(x) ^ ((((uint32_t)(x)) >> 3) & 0x70))

__device__ __forceinline__ void mma16816(float* d,
    uint32_t a0, uint32_t a1, uint32_t a2, uint32_t a3,
    uint32_t b0, uint32_t b1) {
    asm volatile(
        "mma.sync.aligned.m16n8k16.row.col.f32.bf16.bf16.f32 "
        "{%0,%1,%2,%3},{%4,%5,%6,%7},{%8,%9},{%0,%1,%2,%3};"
        : "+f"(d[0]), "+f"(d[1]), "+f"(d[2]), "+f"(d[3])
        : "r"(a0), "r"(a1), "r"(a2), "r"(a3), "r"(b0), "r"(b1));
}
#define LDSM4(r0, r1, r2, r3, a)                                        \
    asm volatile("ldmatrix.sync.aligned.m8n8.x4.shared.b16 "            \
                 "{%0,%1,%2,%3}, [%4];"                                 \
                 : "=r"(r0), "=r"(r1), "=r"(r2), "=r"(r3) : "r"(a))
#define LDSM4T(r0, r1, r2, r3, a)                                       \
    asm volatile("ldmatrix.sync.aligned.m8n8.x4.trans.shared.b16 "      \
                 "{%0,%1,%2,%3}, [%4];"                                 \
                 : "=r"(r0), "=r"(r1), "=r"(r2), "=r"(r3) : "r"(a))
#define CP16(dst, src)                                                  \
    asm volatile("cp.async.cg.shared.global [%0], [%1], 16;"            \
                 :: "r"(dst), "l"(src))
#define CP_COMMIT() asm volatile("cp.async.commit_group;" ::: "memory")

__device__ __forceinline__ float ex2f(float x) {
    float r;
    asm("ex2.approx.ftz.f32 %0, %1;" : "=f"(r) : "f"(x));
    return r;
}

// Pack p0 (lo) / p1 (hi) into bf16x2 hi-part + exact fp32 residual bf16x2.
__device__ __forceinline__ void packbf(float p0, float p1,
                                       uint32_t& hv, uint32_t& rv) {
    asm("cvt.rn.bf16x2.f32 %0, %1, %2;" : "=r"(hv) : "f"(p1), "f"(p0));
    float h0 = __uint_as_float(hv << 16);
    float h1 = __uint_as_float(hv & 0xFFFF0000u);
    asm("cvt.rn.bf16x2.f32 %0, %1, %2;" : "=r"(rv) : "f"(p1 - h1), "f"(p0 - h0));
}

__device__ __forceinline__ void splitbf(float x, __nv_bfloat16& h, __nv_bfloat16& l) {
    h = __float2bfloat16(x);
    l = __float2bfloat16(x - __bfloat162float(h));
}

// ===========================================================================
// Stage 1: ONE heterogeneous launch.
//   blockIdx < 128   : projection CTAs — bf16 3-pass HMMA GEMM + splits + norms
//   blockIdx >= 128  : 2048 mask-packing CTAs (DRAM-bound streaming)
// ===========================================================================
#define PROJ_CTAS 128
#define MASK_CTAS 2048

// proj smem tiles (bf16, 64x64, 128B rows, SW128): Xhi Xlo Whi0 Wlo0 Whi1 Wlo1
#define PX_HI  0
#define PX_LO  8192
#define PW_HI0 16384
#define PW_LO0 24576
#define PW_HI1 32768
#define PW_LO1 40960

__global__ void __launch_bounds__(256) prep_kernel(const float* __restrict__ inp,
                                                   const float* __restrict__ kW,
                                                   const float* __restrict__ vW,
                                                   const int* __restrict__ adj) {
    __shared__ __align__(16) char psm[49152];
    const int tid = threadIdx.x;

    if (blockIdx.x >= PROJ_CTAS) {
        // ---- mask role: warp packs 128 consecutive 32-key words, MLP=16.
        const int warp = ((blockIdx.x - PROJ_CTAS) * 256 + tid) >> 5;
        const int lane = tid & 31;
        const long base = (long)warp * 128;
        for (int i0 = 0; i0 < 128; i0 += 16) {
            int v[16];
            #pragma unroll
            for (int u = 0; u < 16; u++)
                v[u] = adj[(base + i0 + u) * 32 + lane];
            #pragma unroll
            for (int u = 0; u < 16; u++) {
                unsigned b = __ballot_sync(0xffffffffu, v[u] > 0);
                if (lane == 0) g_mask[base + i0 + u] = b;
            }
        }
        return;
    }

    // ---- projection role: HMMA bf16 3-pass GEMM, 64 rows, N=128 (kW|vW).
    if (blockIdx.x == 0 && tid == 0) g_maxnorm_bits = 0u;
    const uint32_t sbp = smem_u32(psm);
    const int w = tid >> 5, lane = tid & 31;
    const int mband = w & 3;             // 4 m-bands of 16 rows
    const int nhalf = w >> 2;            // 0 -> kW, 1 -> vW
    const int g = lane >> 2, tg = lane & 3;
    const int rbase = blockIdx.x * 64;

    const int arow  = mband * 16 + ((lane >> 3) & 1) * 8 + (lane & 7);
    const int acol0 = (lane >> 4) * 8;
    const int vrow_l = ((lane >> 3) & 1) * 8 + (lane & 7);
    const int vcol_l = (lane >> 4) * 8;

    float o[8][4];
    #pragma unroll
    for (int i = 0; i < 8; i++)
        #pragma unroll
        for (int j = 0; j < 4; j++) o[i][j] = 0.f;

    for (int kc = 0; kc < DIN; kc += 64) {
        __syncthreads();
        // stage X chunk (64 rows x 64 k) as bf16 hi/lo
        for (int e = tid; e < 4096; e += 256) {
            int r = e >> 6, c = e & 63;
            float x = inp[(rbase + r) * DIN + kc + c];
            __nv_bfloat16 h, l;
            splitbf(x, h, l);
            uint32_t sw = SW128(r * 128 + c * 2);
            *(__nv_bfloat16*)(psm + PX_HI + sw) = h;
            *(__nv_bfloat16*)(psm + PX_LO + sw) = l;
        }
        // stage W chunks: kW -> tiles 0, vW -> tiles 1 (64 k x 64 n each)
        for (int e = tid; e < 4096; e += 256) {
            int r = e >> 6, c = e & 63;
            uint32_t sw = SW128(r * 128 + c * 2);
            __nv_bfloat16 h, l;
            splitbf(kW[(kc + r) * DD + c], h, l);
            *(__nv_bfloat16*)(psm + PW_HI0 + sw) = h;
            *(__nv_bfloat16*)(psm + PW_LO0 + sw) = l;
            splitbf(vW[(kc + r) * DD + c], h, l);
            *(__nv_bfloat16*)(psm + PW_HI1 + sw) = h;
            *(__nv_bfloat16*)(psm + PW_LO1 + sw) = l;
        }
        __syncthreads();

        const uint32_t whi = sbp + (nhalf ? PW_HI1 : PW_HI0);
        const uint32_t wlo = sbp + (nhalf ? PW_LO1 : PW_LO0);
        #pragma unroll
        for (int ks = 0; ks < 4; ks++) {
            uint32_t swA = SW128(arow * 128 + (ks * 16 + acol0) * 2);
            uint32_t a0, a1, a2, a3, l0, l1, l2, l3;
            LDSM4(a0, a1, a2, a3, sbp + PX_HI + swA);
            LDSM4(l0, l1, l2, l3, sbp + PX_LO + swA);
            #pragma unroll
            for (int np = 0; np < 4; np++) {
                uint32_t swB = SW128((ks * 16 + vrow_l) * 128 +
                                     (np * 16 + vcol_l) * 2);
                uint32_t v0, v1, v2, v3;
                LDSM4T(v0, v1, v2, v3, whi + swB);
                mma16816(o[2*np],   a0, a1, a2, a3, v0, v1);
                mma16816(o[2*np+1], a0, a1, a2, a3, v2, v3);
                mma16816(o[2*np],   l0, l1, l2, l3, v0, v1);
                mma16816(o[2*np+1], l0, l1, l2, l3, v2, v3);
                uint32_t u0, u1, u2, u3;
                LDSM4T(u0, u1, u2, u3, wlo + swB);
                mma16816(o[2*np],   a0, a1, a2, a3, u0, u1);
                mma16816(o[2*np+1], a0, a1, a2, a3, u2, u3);
            }
        }
    }

    // epilogue: splits + (kh-half) fused norms
    const int gr0 = rbase + mband * 16 + g;
    const int gr1 = gr0 + 8;
    if (nhalf == 0) {
        float p0 = 0.f, p1 = 0.f;
        #pragma unroll
        for (int nt = 0; nt < 8; nt++) {
            int col = nt * 8 + 2 * tg;
            __nv_bfloat16 h, l;
            splitbf(o[nt][0], h, l);
            g_khhi[gr0 * DD + col] = h;     g_khlo[gr0 * DD + col] = l;
            splitbf(o[nt][1], h, l);
            g_khhi[gr0 * DD + col + 1] = h; g_khlo[gr0 * DD + col + 1] = l;
            splitbf(o[nt][2], h, l);
            g_khhi[gr1 * DD + col] = h;     g_khlo[gr1 * DD + col] = l;
            splitbf(o[nt][3], h, l);
            g_khhi[gr1 * DD + col + 1] = h; g_khlo[gr1 * DD + col + 1] = l;
            p0 = fmaf(o[nt][0], o[nt][0], fmaf(o[nt][1], o[nt][1], p0));
            p1 = fmaf(o[nt][2], o[nt][2], fmaf(o[nt][3], o[nt][3], p1));
        }
        p0 += __shfl_xor_sync(0xffffffffu, p0, 1);
        p0 += __shfl_xor_sync(0xffffffffu, p0, 2);
        p1 += __shfl_xor_sync(0xffffffffu, p1, 1);
        p1 += __shfl_xor_sync(0xffffffffu, p1, 2);
        if (tg == 0) {
            float n0 = sqrtf(p0), n1 = sqrtf(p1);
            g_norm[gr0] = n0;
            g_norm[gr1] = n1;
            atomicMax(&g_maxnorm_bits, __float_as_uint(n0));
            atomicMax(&g_maxnorm_bits, __float_as_uint(n1));
        }
    } else {
        #pragma unroll
        for (int nt = 0; nt < 8; nt++) {
            int col = nt * 8 + 2 * tg;
            __nv_bfloat16 h, l;
            splitbf(o[nt][0], h, l);
            g_vhhi[gr0 * DD + col] = h;     g_vhlo[gr0 * DD + col] = l;
            splitbf(o[nt][1], h, l);
            g_vhhi[gr0 * DD + col + 1] = h; g_vhlo[gr0 * DD + col + 1] = l;
            splitbf(o[nt][2], h, l);
            g_vhhi[gr1 * DD + col] = h;     g_vhlo[gr1 * DD + col] = l;
            splitbf(o[nt][3], h, l);
            g_vhhi[gr1 * DD + col + 1] = h; g_vhlo[gr1 * DD + col + 1] = l;
        }
    }
}

// ===========================================================================
// Stage 2: HMMA flash attention, fixed per-row max (unchanged, 161us proven).
// grid = 128 (64 q rows / CTA), 512 threads (16 warps).
// warp w: q-band (w&3)*16, key quarter (w>>2)*32 within each 128-key tile.
// S: bf16 3-pass.  PV: bf16 3-pass.
// smem: 3-slot cp.async ring (Khi|Klo|Vhi|Vlo, 16KB each) = 192KB.
// ===========================================================================
#define SLOT_BYTES 65536
#define OFF_KHI 0
#define OFF_KLO 16384
#define OFF_VHI 32768
#define OFF_VLO 49152
#define NSLOTS 3
#define SMEM_ATTN (NSLOTS * SLOT_BYTES)
#define TILES (NN / 128)

__device__ __forceinline__ void fill_tile(uint32_t sb, int slot, int kbase, int tid) {
    const uint32_t base = sb + slot * SLOT_BYTES;
    #pragma unroll
    for (int i = 0; i < 2; i++) {
        int e = i * 512 + tid;          // 1024 16B units per array
        int r = e >> 3, b = e & 7;
        uint32_t sw = SW128(r * 128 + b * 16);
        long src = (long)(kbase + r) * DD + b * 8;
        CP16(base + OFF_KHI + sw, g_khhi + src);
        CP16(base + OFF_KLO + sw, g_khlo + src);
        CP16(base + OFF_VHI + sw, g_vhhi + src);
        CP16(base + OFF_VLO + sw, g_vhlo + src);
    }
}

__global__ void __launch_bounds__(512, 1)
attn_kernel(float* __restrict__ out) {
    extern __shared__ char smem[];
    const uint32_t sb = smem_u32(smem);
    const int tid  = threadIdx.x;
    const int w    = tid >> 5;
    const int lane = tid & 31;
    const int wq   = w & 3;              // q band
    const int wh   = w >> 2;             // key quarter (0..3)
    const int g    = lane >> 2;
    const int tg   = lane & 3;
    const int q0   = wq * 16;
    const int qbase = blockIdx.x * 64;

    // ---- Stage Q in slot0 (hi at 0, lo at +8192), extract A fragments.
    {
        int e = tid;                     // 512 16B units
        int r = e >> 3, b = e & 7;
        uint32_t sw = SW128(r * 128 + b * 16);
        *(uint4*)(smem + sw) =
            *(const uint4*)(g_khhi + (qbase + r) * DD + b * 8);
        *(uint4*)(smem + 8192 + sw) =
            *(const uint4*)(g_khlo + (qbase + r) * DD + b * 8);
    }
    __syncthreads();

    uint32_t qh[16], ql[16];
    {
        int arow = q0 + ((lane >> 3) & 1) * 8 + (lane & 7);
        int acol0 = (lane >> 4) * 8;
        #pragma unroll
        for (int ks = 0; ks < 4; ks++) {
            uint32_t sw = SW128(arow * 128 + (ks * 16 + acol0) * 2);
            LDSM4(qh[4*ks], qh[4*ks+1], qh[4*ks+2], qh[4*ks+3], sb + sw);
            LDSM4(ql[4*ks], ql[4*ks+1], ql[4*ks+2], ql[4*ks+3], sb + 8192 + sw);
        }
    }
    __syncthreads();

    // Prologue fills for tiles 0 and 1.
    fill_tile(sb, 0, 0, tid);
    CP_COMMIT();
    fill_tile(sb, 1, 128, tid);
    CP_COMMIT();

    // exp in log2 domain: p = 2^(s*c - m')  with c = 0.125*log2e.
    const float C_LOG2E = 1.4426950408889634f;
    const float sc = 0.125f * C_LOG2E;
    const float maxn = __uint_as_float(g_maxnorm_bits) * 0.125f * 1.0001f * C_LOG2E;
    const float mq0 = g_norm[qbase + q0 + g] * maxn;
    const float mq1 = g_norm[qbase + q0 + g + 8] * maxn;
    const unsigned* mrow0 = g_mask + (long)(qbase + q0 + g) * (NN / 32) + wh;
    const unsigned* mrow1 = g_mask + (long)(qbase + q0 + g + 8) * (NN / 32) + wh;

    float o[8][4];
    #pragma unroll
    for (int i = 0; i < 8; i++)
        #pragma unroll
        for (int j = 0; j < 4; j++) o[i][j] = 0.f;
    float l0 = 0.f, l1 = 0.f;

    const int krow_l = (lane >> 4) * 8 + (lane & 7);
    const int kcol_l = ((lane >> 3) & 1) * 8;
    const int vrow_l = ((lane >> 3) & 1) * 8 + (lane & 7);
    const int vcol_l = (lane >> 4) * 8;

    for (int t = 0; t < TILES; t++) {
        const uint32_t tbase = sb + (t % NSLOTS) * SLOT_BYTES;

        unsigned mw0 = mrow0[t * 4];
        unsigned mw1 = mrow1[t * 4];

        if (t + 1 < TILES) asm volatile("cp.async.wait_group 1;" ::: "memory");
        else               asm volatile("cp.async.wait_group 0;" ::: "memory");
        __syncthreads();

        if (t + 2 < TILES) { fill_tile(sb, (t + 2) % NSLOTS, (t + 2) * 128, tid); CP_COMMIT(); }

        // ---- S (bf16 3-pass) + softmax + bf16 P hi/lo pack
        uint32_t ph[2][4], pl[2][4];
        #pragma unroll
        for (int np = 0; np < 2; np++) {
            float s0[4] = {0.f, 0.f, 0.f, 0.f};
            float s1[4] = {0.f, 0.f, 0.f, 0.f};
            #pragma unroll
            for (int ks = 0; ks < 4; ks++) {
                uint32_t sw = SW128((wh * 32 + np * 16 + krow_l) * 128 +
                                    (ks * 16 + kcol_l) * 2);
                uint32_t b0, b1, b2, b3;
                LDSM4(b0, b1, b2, b3, tbase + OFF_KHI + sw);
                mma16816(s0, qh[4*ks], qh[4*ks+1], qh[4*ks+2], qh[4*ks+3], b0, b1);
                mma16816(s1, qh[4*ks], qh[4*ks+1], qh[4*ks+2], qh[4*ks+3], b2, b3);
                mma16816(s0, ql[4*ks], ql[4*ks+1], ql[4*ks+2], ql[4*ks+3], b0, b1);
                mma16816(s1, ql[4*ks], ql[4*ks+1], ql[4*ks+2], ql[4*ks+3], b2, b3);
                uint32_t c0, c1, c2, c3;
                LDSM4(c0, c1, c2, c3, tbase + OFF_KLO + sw);
                mma16816(s0, qh[4*ks], qh[4*ks+1], qh[4*ks+2], qh[4*ks+3], c0, c1);
                mma16816(s1, qh[4*ks], qh[4*ks+1], qh[4*ks+2], qh[4*ks+3], c2, c3);
            }
            int bit = (np << 4) + 2 * tg;
            float p00 = ((mw0 >> bit) & 1u)       ? ex2f(fmaf(s0[0], sc, -mq0)) : 0.f;
            float p01 = ((mw0 >> (bit + 1)) & 1u) ? ex2f(fmaf(s0[1], sc, -mq0)) : 0.f;
            float p02 = ((mw1 >> bit) & 1u)       ? ex2f(fmaf(s0[2], sc, -mq1)) : 0.f;
            float p03 = ((mw1 >> (bit + 1)) & 1u) ? ex2f(fmaf(s0[3], sc, -mq1)) : 0.f;
            float p10 = ((mw0 >> (bit + 8)) & 1u) ? ex2f(fmaf(s1[0], sc, -mq0)) : 0.f;
            float p11 = ((mw0 >> (bit + 9)) & 1u) ? ex2f(fmaf(s1[1], sc, -mq0)) : 0.f;
            float p12 = ((mw1 >> (bit + 8)) & 1u) ? ex2f(fmaf(s1[2], sc, -mq1)) : 0.f;
            float p13 = ((mw1 >> (bit + 9)) & 1u) ? ex2f(fmaf(s1[3], sc, -mq1)) : 0.f;
            l0 += p00 + p01 + p10 + p11;
            l1 += p02 + p03 + p12 + p13;
            packbf(p00, p01, ph[np][0], pl[np][0]);
            packbf(p02, p03, ph[np][1], pl[np][1]);
            packbf(p10, p11, ph[np][2], pl[np][2]);
            packbf(p12, p13, ph[np][3], pl[np][3]);
        }

        // ---- O += P V (bf16 3-pass) over this key quarter
        #pragma unroll
        for (int ks = 0; ks < 2; ks++) {
            #pragma unroll
            for (int np = 0; np < 4; np++) {
                uint32_t sw = SW128((wh * 32 + ks * 16 + vrow_l) * 128 +
                                    (np * 16 + vcol_l) * 2);
                uint32_t v0, v1, v2, v3;
                LDSM4T(v0, v1, v2, v3, tbase + OFF_VHI + sw);
                mma16816(o[2*np],   ph[ks][0], ph[ks][1], ph[ks][2], ph[ks][3], v0, v1);
                mma16816(o[2*np+1], ph[ks][0], ph[ks][1], ph[ks][2], ph[ks][3], v2, v3);
                mma16816(o[2*np],   pl[ks][0], pl[ks][1], pl[ks][2], pl[ks][3], v0, v1);
                mma16816(o[2*np+1], pl[ks][0], pl[ks][1], pl[ks][2], pl[ks][3], v2, v3);
                uint32_t u0, u1, u2, u3;
                LDSM4T(u0, u1, u2, u3, tbase + OFF_VLO + sw);
                mma16816(o[2*np],   ph[ks][0], ph[ks][1], ph[ks][2], ph[ks][3], u0, u1);
                mma16816(o[2*np+1], ph[ks][0], ph[ks][1], ph[ks][2], ph[ks][3], u2, u3);
            }
        }
    }

    // ---- combine 4 key quarters: wh>0 dump partials, wh==0 finalizes.
    __syncthreads();
    float* cmb = (float*)smem;   // 3*128*34 floats = 52KB (slots free now)
    if (wh > 0) {
        float* dst = cmb + ((wh - 1) * 128 + wq * 32 + lane) * 34;
        #pragma unroll
        for (int i = 0; i < 8; i++)
            #pragma unroll
            for (int j = 0; j < 4; j++) dst[i * 4 + j] = o[i][j];
        dst[32] = l0;
        dst[33] = l1;
    }
    __syncthreads();
    if (wh == 0) {
        #pragma unroll
        for (int q = 0; q < 3; q++) {
            const float* src = cmb + (q * 128 + wq * 32 + lane) * 34;
            #pragma unroll
            for (int i = 0; i < 8; i++)
                #pragma unroll
                for (int j = 0; j < 4; j++) o[i][j] += src[i * 4 + j];
            l0 += src[32];
            l1 += src[33];
        }
        l0 += __shfl_xor_sync(0xffffffffu, l0, 1);
        l0 += __shfl_xor_sync(0xffffffffu, l0, 2);
        l1 += __shfl_xor_sync(0xffffffffu, l1, 1);
        l1 += __shfl_xor_sync(0xffffffffu, l1, 2);
        float inv0 = 1.f / l0, inv1 = 1.f / l1;

        int gr0 = qbase + q0 + g, gr1 = gr0 + 8;
        #pragma unroll
        for (int nt = 0; nt < 8; nt++) {
            float x0 = o[nt][0] * inv0; x0 = (x0 > 0.f) ? x0 : expm1f(x0);
            float x1 = o[nt][1] * inv0; x1 = (x1 > 0.f) ? x1 : expm1f(x1);
            float x2 = o[nt][2] * inv1; x2 = (x2 > 0.f) ? x2 : expm1f(x2);
            float x3 = o[nt][3] * inv1; x3 = (x3 > 0.f) ? x3 : expm1f(x3);
            *(float2*)(out + (long)gr0 * DD + nt * 8 + 2 * tg) = make_float2(x0, x1);
            *(float2*)(out + (long)gr1 * DD + nt * 8 + 2 * tg) = make_float2(x2, x3);
        }
    }
}

namespace {
struct AttrInit {
    AttrInit() {
        cudaFuncSetAttribute(attn_kernel,
                             cudaFuncAttributeMaxDynamicSharedMemorySize,
                             SMEM_ATTN);
    }
} attr_init_;
}

extern "C" void kernel_launch(void* const* d_in, const int* in_sizes, int n_in,
                              void* d_out, int out_size) {
    const float* inp = nullptr;
    const int*   adj = nullptr;
    const float* kW  = nullptr;
    const float* vW  = nullptr;
    for (int i = 0; i < n_in; i++) {
        long sz = in_sizes[i];
        if (sz == (long)NN * DIN)      inp = (const float*)d_in[i];
        else if (sz == (long)NN * NN)  adj = (const int*)d_in[i];
        else if (sz == (long)DIN * DD) { if (!kW) kW = (const float*)d_in[i];
                                         else     vW = (const float*)d_in[i]; }
    }
    float* out = (float*)d_out;

    cudaFuncSetAttribute(attn_kernel,
                         cudaFuncAttributeMaxDynamicSharedMemorySize, SMEM_ATTN);

    prep_kernel<<<PROJ_CTAS + MASK_CTAS, 256>>>(inp, kW, vW, adj);
    attn_kernel<<<NN / 64, 512, SMEM_ATTN>>>(out);
}

// round 14
// speedup vs baseline: 1.1228x; 1.1228x over previous
#include <cuda_runtime.h>
#include <cuda_bf16.h>
#include <math.h>
#include <stdint.h>

#define NN   8192
#define DIN  512
#define DD   64

// ===========================================================================
// Device globals (no allocation allowed).
// ===========================================================================
__device__ __nv_bfloat16  g_khhi[NN * DD];
__device__ __nv_bfloat16  g_khlo[NN * DD];
__device__ __nv_bfloat16  g_vhhi[NN * DD];
__device__ __nv_bfloat16  g_vhlo[NN * DD];
__device__ float          g_norm[NN];
__device__ unsigned       g_maxnorm_bits;   // reset in prep CTA0; atomicMax after
__device__ unsigned       g_mask[NN * (NN / 32)];   // 8MB bitmask

// ===========================================================================
// Helpers
// ===========================================================================
__device__ __forceinline__ uint32_t smem_u32(const void* p) {
    uint32_t a;
    asm("{ .reg .u64 t; cvta.to.shared.u64 t, %1; cvt.u32.u64 %0, t; }"
        : "=r"(a) : "l"(p));
    return a;
}
#define SW128(x) ((uint32_t)(x) ^ ((((uint32_t)(x)) >> 3) & 0x70))

__device__ __forceinline__ void mma16816(float* d,
    uint32_t a0, uint32_t a1, uint32_t a2, uint32_t a3,
    uint32_t b0, uint32_t b1) {
    asm volatile(
        "mma.sync.aligned.m16n8k16.row.col.f32.bf16.bf16.f32 "
        "{%0,%1,%2,%3},{%4,%5,%6,%7},{%8,%9},{%0,%1,%2,%3};"
        : "+f"(d[0]), "+f"(d[1]), "+f"(d[2]), "+f"(d[3])
        : "r"(a0), "r"(a1), "r"(a2), "r"(a3), "r"(b0), "r"(b1));
}
#define LDSM4(r0, r1, r2, r3, a)                                        \
    asm volatile("ldmatrix.sync.aligned.m8n8.x4.shared.b16 "            \
                 "{%0,%1,%2,%3}, [%4];"                                 \
                 : "=r"(r0), "=r"(r1), "=r"(r2), "=r"(r3) : "r"(a))
#define LDSM4T(r0, r1, r2, r3, a)                                       \
    asm volatile("ldmatrix.sync.aligned.m8n8.x4.trans.shared.b16 "      \
                 "{%0,%1,%2,%3}, [%4];"                                 \
                 : "=r"(r0), "=r"(r1), "=r"(r2), "=r"(r3) : "r"(a))
#define CP16(dst, src)                                                  \
    asm volatile("cp.async.cg.shared.global [%0], [%1], 16;"            \
                 :: "r"(dst), "l"(src))
#define CP_COMMIT() asm volatile("cp.async.commit_group;" ::: "memory")
#define BAR_GRP(id) asm volatile("bar.sync %0, 128;" :: "r"(id) : "memory")

__device__ __forceinline__ float ex2f(float x) {
    float r;
    asm("ex2.approx.ftz.f32 %0, %1;" : "=f"(r) : "f"(x));
    return r;
}

// Pack p0 (lo) / p1 (hi) into bf16x2 hi-part + exact fp32 residual bf16x2.
__device__ __forceinline__ void packbf(float p0, float p1,
                                       uint32_t& hv, uint32_t& rv) {
    asm("cvt.rn.bf16x2.f32 %0, %1, %2;" : "=r"(hv) : "f"(p1), "f"(p0));
    float h0 = __uint_as_float(hv << 16);
    float h1 = __uint_as_float(hv & 0xFFFF0000u);
    asm("cvt.rn.bf16x2.f32 %0, %1, %2;" : "=r"(rv) : "f"(p1 - h1), "f"(p0 - h0));
}

// ===========================================================================
// Stage 1: ONE heterogeneous launch (round-12 proven version).
//   blockIdx < 128   : projection CTAs (FMA-bound) + fused row norms
//   blockIdx >= 128  : 2048 mask-packing CTAs (DRAM-bound streaming)
// ===========================================================================
#define PROJ_CTAS 128
#define MASK_CTAS 2048

__global__ void __launch_bounds__(256) prep_kernel(const float* __restrict__ inp,
                                                   const float* __restrict__ kW,
                                                   const float* __restrict__ vW,
                                                   const int* __restrict__ adj) {
    const int tid = threadIdx.x;

    if (blockIdx.x >= PROJ_CTAS) {
        // ---- mask role: warp packs 128 consecutive 32-key words, MLP=16.
        const int warp = ((blockIdx.x - PROJ_CTAS) * 256 + tid) >> 5;
        const int lane = tid & 31;
        const long base = (long)warp * 128;
        for (int i0 = 0; i0 < 128; i0 += 16) {
            int v[16];
            #pragma unroll
            for (int u = 0; u < 16; u++)
                v[u] = adj[(base + i0 + u) * 32 + lane];
            #pragma unroll
            for (int u = 0; u < 16; u++) {
                unsigned b = __ballot_sync(0xffffffffu, v[u] > 0);
                if (lane == 0) g_mask[base + i0 + u] = b;
            }
        }
        return;
    }

    // ---- projection role (FFMA, fused bf16 splits + norms).
    __shared__ float sIn[64][36];
    __shared__ float sKW[32][65];
    __shared__ float sVW[32][65];
    const int tx = tid & 15, ty = tid >> 4;
    if (blockIdx.x == 0 && tid == 0) g_maxnorm_bits = 0u;
    const int rbase = blockIdx.x * 64;
    float ak[4][4] = {}, av[4][4] = {};

    for (int kc = 0; kc < DIN; kc += 32) {
        __syncthreads();
        for (int e = tid; e < 64 * 32; e += 256) {
            int r = e >> 5, c = e & 31;
            sIn[r][c] = inp[(rbase + r) * DIN + kc + c];
        }
        for (int e = tid; e < 32 * 64; e += 256) {
            int r = e >> 6, c = e & 63;
            sKW[r][c] = kW[(kc + r) * DD + c];
            sVW[r][c] = vW[(kc + r) * DD + c];
        }
        __syncthreads();
        #pragma unroll 8
        for (int kk = 0; kk < 32; kk++) {
            float a[4], bk[4], bv[4];
            #pragma unroll
            for (int i = 0; i < 4; i++) a[i] = sIn[ty + 16 * i][kk];
            #pragma unroll
            for (int j = 0; j < 4; j++) { bk[j] = sKW[kk][tx + 16 * j];
                                          bv[j] = sVW[kk][tx + 16 * j]; }
            #pragma unroll
            for (int i = 0; i < 4; i++)
                #pragma unroll
                for (int j = 0; j < 4; j++) {
                    ak[i][j] = fmaf(a[i], bk[j], ak[i][j]);
                    av[i][j] = fmaf(a[i], bv[j], av[i][j]);
                }
        }
    }

    #pragma unroll
    for (int i = 0; i < 4; i++) {
        float part = 0.f;
        #pragma unroll
        for (int j = 0; j < 4; j++) {
            int idx = (rbase + ty + 16 * i) * DD + tx + 16 * j;
            float kv = ak[i][j], vv = av[i][j];
            part = fmaf(kv, kv, part);
            __nv_bfloat16 kh = __float2bfloat16(kv);
            g_khhi[idx] = kh;
            g_khlo[idx] = __float2bfloat16(kv - __bfloat162float(kh));
            __nv_bfloat16 vh = __float2bfloat16(vv);
            g_vhhi[idx] = vh;
            g_vhlo[idx] = __float2bfloat16(vv - __bfloat162float(vh));
        }
        #pragma unroll
        for (int off = 1; off < 16; off <<= 1)
            part += __shfl_xor_sync(0xffffffffu, part, off);
        if (tx == 0) {
            float n = sqrtf(part);
            g_norm[rbase + ty + 16 * i] = n;
            atomicMax(&g_maxnorm_bits, __float_as_uint(n));
        }
    }
}

// ===========================================================================
// Stage 2: HMMA flash attention, fixed per-row max.
// grid = 128 (64 q rows / CTA), 512 threads (16 warps).
// warp w: q-band (w&3)*16, key quarter wh=(w>>2)*32.
// PER-GROUP PIPELINES: each key-quarter group (4 warps, 128 threads) owns a
// private 3-slot cp.async ring (16KB/slot) and syncs with a NAMED barrier
// (bar.sync wh+1, 128). SMSP p hosts one warp of each group, so the groups
// drift out of phase and fill each other's tensor-pipe bubbles.
// ===========================================================================
#define GSLOT 16384                  // per-group slot: Kq hi/lo + Vq hi/lo
#define GOFF_KHI 0
#define GOFF_KLO 4096
#define GOFF_VHI 8192
#define GOFF_VLO 12288
#define NSLOTS 3
#define GRP_BYTES (NSLOTS * GSLOT)   // 48KB per group
#define SMEM_ATTN (4 * GRP_BYTES)    // 192KB
#define TILES (NN / 128)

// Fill this group's 32-key quarter of tile with keys [kq, kq+32).
__device__ __forceinline__ void fill_quarter(uint32_t gslot, int kq, int ltid) {
    #pragma unroll
    for (int i = 0; i < 2; i++) {
        int e = i * 128 + ltid;      // 256 16B units per array
        int r = e >> 3, b = e & 7;
        uint32_t sw = SW128(r * 128 + b * 16);
        long src = (long)(kq + r) * DD + b * 8;
        CP16(gslot + GOFF_KHI + sw, g_khhi + src);
        CP16(gslot + GOFF_KLO + sw, g_khlo + src);
        CP16(gslot + GOFF_VHI + sw, g_vhhi + src);
        CP16(gslot + GOFF_VLO + sw, g_vhlo + src);
    }
}

__global__ void __launch_bounds__(512, 1)
attn_kernel(float* __restrict__ out) {
    extern __shared__ char smem[];
    const uint32_t sb = smem_u32(smem);
    const int tid  = threadIdx.x;
    const int w    = tid >> 5;
    const int lane = tid & 31;
    const int wq   = w & 3;              // q band
    const int wh   = w >> 2;             // key quarter (0..3) == group
    const int ltid = tid & 127;          // thread id within group
    const int g    = lane >> 2;
    const int tg   = lane & 3;
    const int q0   = wq * 16;
    const int qbase = blockIdx.x * 64;
    const uint32_t gbase = sb + wh * GRP_BYTES;

    // ---- Stage Q at sb (hi) / sb+8192 (lo), extract A fragments.
    {
        int e = tid;                     // 512 16B units
        int r = e >> 3, b = e & 7;
        uint32_t sw = SW128(r * 128 + b * 16);
        *(uint4*)(smem + sw) =
            *(const uint4*)(g_khhi + (qbase + r) * DD + b * 8);
        *(uint4*)(smem + 8192 + sw) =
            *(const uint4*)(g_khlo + (qbase + r) * DD + b * 8);
    }
    __syncthreads();

    uint32_t qh[16], ql[16];
    {
        int arow = q0 + ((lane >> 3) & 1) * 8 + (lane & 7);
        int acol0 = (lane >> 4) * 8;
        #pragma unroll
        for (int ks = 0; ks < 4; ks++) {
            uint32_t sw = SW128(arow * 128 + (ks * 16 + acol0) * 2);
            LDSM4(qh[4*ks], qh[4*ks+1], qh[4*ks+2], qh[4*ks+3], sb + sw);
            LDSM4(ql[4*ks], ql[4*ks+1], ql[4*ks+2], ql[4*ks+3], sb + 8192 + sw);
        }
    }
    __syncthreads();   // Q region free (overlaps group 0 slots)

    // Prologue fills for tiles 0 and 1 (this group's quarters).
    fill_quarter(gbase + 0 * GSLOT, 0 * 128 + wh * 32, ltid);
    CP_COMMIT();
    fill_quarter(gbase + 1 * GSLOT, 1 * 128 + wh * 32, ltid);
    CP_COMMIT();

    // exp in log2 domain: p = 2^(s*c - m').
    const float C_LOG2E = 1.4426950408889634f;
    const float sc = 0.125f * C_LOG2E;
    const float maxn = __uint_as_float(g_maxnorm_bits) * 0.125f * 1.0001f * C_LOG2E;
    const float mq0 = g_norm[qbase + q0 + g] * maxn;
    const float mq1 = g_norm[qbase + q0 + g + 8] * maxn;
    const unsigned* mrow0 = g_mask + (long)(qbase + q0 + g) * (NN / 32) + wh;
    const unsigned* mrow1 = g_mask + (long)(qbase + q0 + g + 8) * (NN / 32) + wh;

    float o[8][4];
    #pragma unroll
    for (int i = 0; i < 8; i++)
        #pragma unroll
        for (int j = 0; j < 4; j++) o[i][j] = 0.f;
    float l0 = 0.f, l1 = 0.f;

    const int krow_l = (lane >> 4) * 8 + (lane & 7);
    const int kcol_l = ((lane >> 3) & 1) * 8;
    const int vrow_l = ((lane >> 3) & 1) * 8 + (lane & 7);
    const int vcol_l = (lane >> 4) * 8;

    for (int t = 0; t < TILES; t++) {
        const uint32_t tbase = gbase + (t % NSLOTS) * GSLOT;

        unsigned mw0 = mrow0[t * 4];
        unsigned mw1 = mrow1[t * 4];

        // wait for this group's tile-t fill, sync the group only.
        if (t + 1 < TILES) asm volatile("cp.async.wait_group 1;" ::: "memory");
        else               asm volatile("cp.async.wait_group 0;" ::: "memory");
        BAR_GRP(wh + 1);

        if (t + 2 < TILES) {
            fill_quarter(gbase + ((t + 2) % NSLOTS) * GSLOT,
                         (t + 2) * 128 + wh * 32, ltid);
            CP_COMMIT();
        }

        // ---- S (bf16 3-pass) + softmax + bf16 P hi/lo pack
        uint32_t ph[2][4], pl[2][4];
        #pragma unroll
        for (int np = 0; np < 2; np++) {
            float s0[4] = {0.f, 0.f, 0.f, 0.f};
            float s1[4] = {0.f, 0.f, 0.f, 0.f};
            #pragma unroll
            for (int ks = 0; ks < 4; ks++) {
                uint32_t sw = SW128((np * 16 + krow_l) * 128 +
                                    (ks * 16 + kcol_l) * 2);
                uint32_t b0, b1, b2, b3;
                LDSM4(b0, b1, b2, b3, tbase + GOFF_KHI + sw);
                mma16816(s0, qh[4*ks], qh[4*ks+1], qh[4*ks+2], qh[4*ks+3], b0, b1);
                mma16816(s1, qh[4*ks], qh[4*ks+1], qh[4*ks+2], qh[4*ks+3], b2, b3);
                mma16816(s0, ql[4*ks], ql[4*ks+1], ql[4*ks+2], ql[4*ks+3], b0, b1);
                mma16816(s1, ql[4*ks], ql[4*ks+1], ql[4*ks+2], ql[4*ks+3], b2, b3);
                uint32_t c0, c1, c2, c3;
                LDSM4(c0, c1, c2, c3, tbase + GOFF_KLO + sw);
                mma16816(s0, qh[4*ks], qh[4*ks+1], qh[4*ks+2], qh[4*ks+3], c0, c1);
                mma16816(s1, qh[4*ks], qh[4*ks+1], qh[4*ks+2], qh[4*ks+3], c2, c3);
            }
            int bit = (np << 4) + 2 * tg;
            float p00 = ((mw0 >> bit) & 1u)       ? ex2f(fmaf(s0[0], sc, -mq0)) : 0.f;
            float p01 = ((mw0 >> (bit + 1)) & 1u) ? ex2f(fmaf(s0[1], sc, -mq0)) : 0.f;
            float p02 = ((mw1 >> bit) & 1u)       ? ex2f(fmaf(s0[2], sc, -mq1)) : 0.f;
            float p03 = ((mw1 >> (bit + 1)) & 1u) ? ex2f(fmaf(s0[3], sc, -mq1)) : 0.f;
            float p10 = ((mw0 >> (bit + 8)) & 1u) ? ex2f(fmaf(s1[0], sc, -mq0)) : 0.f;
            float p11 = ((mw0 >> (bit + 9)) & 1u) ? ex2f(fmaf(s1[1], sc, -mq0)) : 0.f;
            float p12 = ((mw1 >> (bit + 8)) & 1u) ? ex2f(fmaf(s1[2], sc, -mq1)) : 0.f;
            float p13 = ((mw1 >> (bit + 9)) & 1u) ? ex2f(fmaf(s1[3], sc, -mq1)) : 0.f;
            l0 += p00 + p01 + p10 + p11;
            l1 += p02 + p03 + p12 + p13;
            packbf(p00, p01, ph[np][0], pl[np][0]);
            packbf(p02, p03, ph[np][1], pl[np][1]);
            packbf(p10, p11, ph[np][2], pl[np][2]);
            packbf(p12, p13, ph[np][3], pl[np][3]);
        }

        // ---- O += P V (bf16 3-pass) over this key quarter
        #pragma unroll
        for (int ks = 0; ks < 2; ks++) {
            #pragma unroll
            for (int np = 0; np < 4; np++) {
                uint32_t sw = SW128((ks * 16 + vrow_l) * 128 +
                                    (np * 16 + vcol_l) * 2);
                uint32_t v0, v1, v2, v3;
                LDSM4T(v0, v1, v2, v3, tbase + GOFF_VHI + sw);
                mma16816(o[2*np],   ph[ks][0], ph[ks][1], ph[ks][2], ph[ks][3], v0, v1);
                mma16816(o[2*np+1], ph[ks][0], ph[ks][1], ph[ks][2], ph[ks][3], v2, v3);
                mma16816(o[2*np],   pl[ks][0], pl[ks][1], pl[ks][2], pl[ks][3], v0, v1);
                mma16816(o[2*np+1], pl[ks][0], pl[ks][1], pl[ks][2], pl[ks][3], v2, v3);
                uint32_t u0, u1, u2, u3;
                LDSM4T(u0, u1, u2, u3, tbase + GOFF_VLO + sw);
                mma16816(o[2*np],   ph[ks][0], ph[ks][1], ph[ks][2], ph[ks][3], u0, u1);
                mma16816(o[2*np+1], ph[ks][0], ph[ks][1], ph[ks][2], ph[ks][3], u2, u3);
            }
        }
    }

    // ---- combine 4 key quarters: wh>0 dump partials, wh==0 finalizes.
    __syncthreads();
    float* cmb = (float*)smem;   // 3*128*34 floats = 52KB (slots free now)
    if (wh > 0) {
        float* dst = cmb + ((wh - 1) * 128 + wq * 32 + lane) * 34;
        #pragma unroll
        for (int i = 0; i < 8; i++)
            #pragma unroll
            for (int j = 0; j < 4; j++) dst[i * 4 + j] = o[i][j];
        dst[32] = l0;
        dst[33] = l1;
    }
    __syncthreads();
    if (wh == 0) {
        #pragma unroll
        for (int q = 0; q < 3; q++) {
            const float* src = cmb + (q * 128 + wq * 32 + lane) * 34;
            #pragma unroll
            for (int i = 0; i < 8; i++)
                #pragma unroll
                for (int j = 0; j < 4; j++) o[i][j] += src[i * 4 + j];
            l0 += src[32];
            l1 += src[33];
        }
        l0 += __shfl_xor_sync(0xffffffffu, l0, 1);
        l0 += __shfl_xor_sync(0xffffffffu, l0, 2);
        l1 += __shfl_xor_sync(0xffffffffu, l1, 1);
        l1 += __shfl_xor_sync(0xffffffffu, l1, 2);
        float inv0 = 1.f / l0, inv1 = 1.f / l1;

        int gr0 = qbase + q0 + g, gr1 = gr0 + 8;
        #pragma unroll
        for (int nt = 0; nt < 8; nt++) {
            float x0 = o[nt][0] * inv0; x0 = (x0 > 0.f) ? x0 : expm1f(x0);
            float x1 = o[nt][1] * inv0; x1 = (x1 > 0.f) ? x1 : expm1f(x1);
            float x2 = o[nt][2] * inv1; x2 = (x2 > 0.f) ? x2 : expm1f(x2);
            float x3 = o[nt][3] * inv1; x3 = (x3 > 0.f) ? x3 : expm1f(x3);
            *(float2*)(out + (long)gr0 * DD + nt * 8 + 2 * tg) = make_float2(x0, x1);
            *(float2*)(out + (long)gr1 * DD + nt * 8 + 2 * tg) = make_float2(x2, x3);
        }
    }
}

namespace {
struct AttrInit {
    AttrInit() {
        cudaFuncSetAttribute(attn_kernel,
                             cudaFuncAttributeMaxDynamicSharedMemorySize,
                             SMEM_ATTN);
    }
} attr_init_;
}

extern "C" void kernel_launch(void* const* d_in, const int* in_sizes, int n_in,
                              void* d_out, int out_size) {
    const float* inp = nullptr;
    const int*   adj = nullptr;
    const float* kW  = nullptr;
    const float* vW  = nullptr;
    for (int i = 0; i < n_in; i++) {
        long sz = in_sizes[i];
        if (sz == (long)NN * DIN)      inp = (const float*)d_in[i];
        else if (sz == (long)NN * NN)  adj = (const int*)d_in[i];
        else if (sz == (long)DIN * DD) { if (!kW) kW = (const float*)d_in[i];
                                         else     vW = (const float*)d_in[i]; }
    }
    float* out = (float*)d_out;

    cudaFuncSetAttribute(attn_kernel,
                         cudaFuncAttributeMaxDynamicSharedMemorySize, SMEM_ATTN);

    prep_kernel<<<PROJ_CTAS + MASK_CTAS, 256>>>(inp, kW, vW, adj);
    attn_kernel<<<NN / 64, 512, SMEM_ATTN>>>(out);
}